// round 11
// baseline (speedup 1.0000x reference)
#include <cuda_runtime.h>
#include <cstdint>
#include <math.h>

// Problem constants: B=4, C=256, H=W=64 -> N=4096, num_heads=1, d=256
#define NB    4
#define NC    256
#define NN    4096
#define NGRP  32

static __device__ float g_xn[NB * NC * NN];
static __device__ float g_qT[NB * NN * NC];   // [b][i][c], q pre-scaled by d^-0.5
static __device__ float g_kT[NB * NN * NC];   // [b][i][c]
static __device__ float g_v [NB * NC * NN];   // [b][c][i]
static __device__ float g_o [NB * NC * NN];
static __device__ float g_S [(size_t)NB * NN * NN];   // 256 MB scores / probs

// flags: [0] = bad-S sample count, [1] = bad-AV sample count
static __device__ int g_flags[2];

static constexpr size_t STR_CN = (size_t)NC * NN;     // 1048576
static constexpr size_t STR_NN = (size_t)NN * NN;     // 16777216

__global__ void init_flags() { g_flags[0] = 0; g_flags[1] = 0; }

// ===========================================================================
// GroupNorm (round-1 proven)
// ===========================================================================
__global__ void __launch_bounds__(256) gn_kernel(const float* __restrict__ x,
                                                 const float* __restrict__ w,
                                                 const float* __restrict__ b) {
    int batch = blockIdx.x >> 5;
    int grp   = blockIdx.x & 31;
    const float* xp = x    + ((size_t)batch * NC + grp * 8) * NN;
    float*       op = g_xn + ((size_t)batch * NC + grp * 8) * NN;
    int tid = threadIdx.x;

    float s = 0.f, s2 = 0.f;
    #pragma unroll 4
    for (int i = tid; i < 8192; i += 256) {
        float4 t = reinterpret_cast<const float4*>(xp)[i];
        s  += t.x + t.y + t.z + t.w;
        s2 += t.x * t.x + t.y * t.y + t.z * t.z + t.w * t.w;
    }
    __shared__ float rs[8], rs2[8];
    __shared__ float sh_mean, sh_rstd;
    int lane = tid & 31, wid = tid >> 5;
    #pragma unroll
    for (int o = 16; o; o >>= 1) {
        s  += __shfl_xor_sync(0xffffffffu, s,  o);
        s2 += __shfl_xor_sync(0xffffffffu, s2, o);
    }
    if (lane == 0) { rs[wid] = s; rs2[wid] = s2; }
    __syncthreads();
    if (tid == 0) {
        float ts = 0.f, ts2 = 0.f;
        #pragma unroll
        for (int i = 0; i < 8; i++) { ts += rs[i]; ts2 += rs2[i]; }
        float mean = ts * (1.0f / 32768.0f);
        float var  = ts2 * (1.0f / 32768.0f) - mean * mean;
        sh_mean = mean;
        sh_rstd = rsqrtf(var + 1e-5f);
    }
    __syncthreads();
    float mean = sh_mean, rstd = sh_rstd;

    #pragma unroll 4
    for (int i = tid; i < 8192; i += 256) {
        int c = grp * 8 + (i >> 10);
        float sc = rstd * w[c];
        float shf = b[c] - mean * sc;
        float4 t = reinterpret_cast<const float4*>(xp)[i];
        t.x = t.x * sc + shf; t.y = t.y * sc + shf;
        t.z = t.z * sc + shf; t.w = t.w * sc + shf;
        reinterpret_cast<float4*>(op)[i] = t;
    }
}

// ===========================================================================
// fp32 tiled GEMM (round-1 proven core). OP_S / OP_AV are gated fixups.
// All A operands are [M][K] now (A_T). OP_S uses the transposed q/k layouts.
// ===========================================================================
#define OP_QKV  0
#define OP_S    1
#define OP_AV   2
#define OP_PROJ 3

template <int OP>
__global__ void __launch_bounds__(256) gemm_kernel(const float* __restrict__ extA,
                                                   const float* __restrict__ bias,
                                                   const float* __restrict__ resid,
                                                   float* __restrict__ extOut) {
    if constexpr (OP == OP_S)  { if (g_flags[0] == 0) return; }
    if constexpr (OP == OP_AV) { if (g_flags[1] == 0) return; }

    constexpr int BM = 128, BN = 64, BK = 32;
    constexpr int K   = (OP == OP_AV) ? 4096 : 256;
    constexpr bool B_T = (OP == OP_S || OP == OP_AV);
    constexpr int LDA = (OP == OP_AV) ? 4096 : 256;
    constexpr int LDB = (OP == OP_S) ? 256 : 4096;

    __shared__ float As[BK][BM + 4];
    __shared__ float Bs[BK][BN + 4];

    size_t bz = blockIdx.z;
    const float* A;
    const float* B;
    if constexpr (OP == OP_QKV)      { A = extA;               B = g_xn + bz * STR_CN; }
    else if constexpr (OP == OP_S)   { A = g_qT + bz * STR_CN; B = g_kT + bz * STR_CN; }
    else if constexpr (OP == OP_AV)  { A = g_v  + bz * STR_CN; B = g_S  + bz * STR_NN; }
    else                             { A = extA;               B = g_o  + bz * STR_CN; }

    int m0 = blockIdx.y * BM;
    int n0 = blockIdx.x * BN;
    int tid = threadIdx.x;
    int tr = tid >> 4;
    int tc = tid & 15;

    float acc[8][4];
    #pragma unroll
    for (int i = 0; i < 8; i++)
        #pragma unroll
        for (int j = 0; j < 4; j++) acc[i][j] = 0.f;

    #pragma unroll 1
    for (int k0 = 0; k0 < K; k0 += BK) {
        {   // A is [M][K]: transpose into As[k][m]
            int m = tid >> 3, kq = tid & 7;
            #pragma unroll
            for (int it = 0; it < 4; ++it, m += 32) {
                float4 va = *reinterpret_cast<const float4*>(&A[(size_t)(m0 + m) * LDA + k0 + kq * 4]);
                As[kq * 4 + 0][m] = va.x;
                As[kq * 4 + 1][m] = va.y;
                As[kq * 4 + 2][m] = va.z;
                As[kq * 4 + 3][m] = va.w;
            }
        }
        if constexpr (B_T) {   // B is [N][K]
            int n = tid >> 3, kq = tid & 7;
            #pragma unroll
            for (int it = 0; it < 2; ++it, n += 32) {
                float4 vb = *reinterpret_cast<const float4*>(&B[(size_t)(n0 + n) * LDB + k0 + kq * 4]);
                Bs[kq * 4 + 0][n] = vb.x;
                Bs[kq * 4 + 1][n] = vb.y;
                Bs[kq * 4 + 2][n] = vb.z;
                Bs[kq * 4 + 3][n] = vb.w;
            }
        } else {               // B is [K][N]
            int kk = tid >> 4, n4 = tid & 15;
            #pragma unroll
            for (int it = 0; it < 2; ++it, kk += 16) {
                float4 vb = *reinterpret_cast<const float4*>(&B[(size_t)(k0 + kk) * LDB + n0 + n4 * 4]);
                *reinterpret_cast<float4*>(&Bs[kk][n4 * 4]) = vb;
            }
        }
        __syncthreads();

        #pragma unroll
        for (int kk = 0; kk < BK; ++kk) {
            float4 a0 = *reinterpret_cast<const float4*>(&As[kk][tr * 8]);
            float4 a1 = *reinterpret_cast<const float4*>(&As[kk][tr * 8 + 4]);
            float4 b0 = *reinterpret_cast<const float4*>(&Bs[kk][tc * 4]);
            float av[8] = {a0.x, a0.y, a0.z, a0.w, a1.x, a1.y, a1.z, a1.w};
            float bv[4] = {b0.x, b0.y, b0.z, b0.w};
            #pragma unroll
            for (int i = 0; i < 8; i++)
                #pragma unroll
                for (int j = 0; j < 4; j++)
                    acc[i][j] = fmaf(av[i], bv[j], acc[i][j]);
        }
        __syncthreads();
    }

    int nbase = n0 + tc * 4;
    if constexpr (OP == OP_QKV) {
        int sec = m0 >> 8;                 // 0=q, 1=k, 2..5=v (m0 in 0..640)
        int cbase = (m0 & 255) + tr * 8;
        float vals[8][4];
        #pragma unroll
        for (int i = 0; i < 8; i++) {
            float bv = bias[m0 + tr * 8 + i];
            #pragma unroll
            for (int j = 0; j < 4; j++) {
                float v = acc[i][j] + bv;
                if (sec == 0) v *= 0.0625f;     // q pre-scaled by d^-0.5
                vals[i][j] = v;
            }
        }
        if (sec < 2) {
            // q/k transposed store: row = spatial index, cols = channels
            float* dT = ((sec == 0) ? g_qT : g_kT) + bz * STR_CN;
            #pragma unroll
            for (int j = 0; j < 4; j++) {
                float4 r0 = make_float4(vals[0][j], vals[1][j], vals[2][j], vals[3][j]);
                float4 r1 = make_float4(vals[4][j], vals[5][j], vals[6][j], vals[7][j]);
                size_t off = (size_t)(nbase + j) * NC + cbase;
                *reinterpret_cast<float4*>(&dT[off])     = r0;
                *reinterpret_cast<float4*>(&dT[off + 4]) = r1;
            }
        } else {
            float* dv = g_v + bz * STR_CN;
            #pragma unroll
            for (int i = 0; i < 8; i++) {
                size_t off = (size_t)(cbase + i) * NN + nbase;
                *reinterpret_cast<float4*>(&dv[off]) =
                    make_float4(vals[i][0], vals[i][1], vals[i][2], vals[i][3]);
            }
        }
    } else if constexpr (OP == OP_S) {
        #pragma unroll
        for (int i = 0; i < 8; i++) {
            int m = m0 + tr * 8 + i;
            *reinterpret_cast<float4*>(&g_S[bz * STR_NN + (size_t)m * NN + nbase]) =
                make_float4(acc[i][0], acc[i][1], acc[i][2], acc[i][3]);
        }
    } else if constexpr (OP == OP_AV) {
        #pragma unroll
        for (int i = 0; i < 8; i++) {
            int m = m0 + tr * 8 + i;
            *reinterpret_cast<float4*>(&g_o[bz * STR_CN + (size_t)m * NN + nbase]) =
                make_float4(acc[i][0], acc[i][1], acc[i][2], acc[i][3]);
        }
    } else {  // OP_PROJ
        #pragma unroll
        for (int i = 0; i < 8; i++) {
            int m = m0 + tr * 8 + i;
            float bv = bias[m];
            size_t off = bz * STR_CN + (size_t)m * NN + nbase;
            float4 xr = *reinterpret_cast<const float4*>(&resid[off]);
            float4 r = make_float4(acc[i][0] + bv + xr.x, acc[i][1] + bv + xr.y,
                                   acc[i][2] + bv + xr.z, acc[i][3] + bv + xr.w);
            *reinterpret_cast<float4*>(&extOut[off]) = r;
        }
    }
}

// ===========================================================================
// k-SIMD f32x2 GEMM: C[m][n] = sum_k A[m][k]*B[n][k], both operands K-major
// with identical leading dim LD. FFMA2 lanes carry adjacent k; operands are
// loaded as ulonglong2 (LDS.128, zero packing movs). Accumulator pairs are
// folded lo+hi in the epilogue.  BM=128, BN=64, BK=32, micro-tile 8x4
// (columns strided tc + 16j for conflict-free b-loads).
// ===========================================================================
static constexpr int PAD_W = 36;   // smem row stride in words (144 B, 16B-aligned)

template <int KTOT, int LD>
__global__ void __launch_bounds__(256) gemm2k_kernel(
    const float* __restrict__ Ag, const float* __restrict__ Bg,
    float* __restrict__ Cg, size_t strA, size_t strB, size_t strC, int ldc) {

    constexpr int BM = 128, BN = 64, BK = 32;
    __shared__ float As[BM * PAD_W];
    __shared__ float Bs[BN * PAD_W];

    size_t bz = blockIdx.z;
    const float* A = Ag + bz * strA;
    const float* B = Bg + bz * strB;
    int m0 = blockIdx.y * BM;
    int n0 = blockIdx.x * BN;
    int tid = threadIdx.x;
    int tr = tid >> 4;        // 0..15 -> rows tr*8 .. +7
    int tc = tid & 15;        // cols tc + 16*j

    unsigned long long acc2[8][4];
    #pragma unroll
    for (int i = 0; i < 8; i++)
        #pragma unroll
        for (int j = 0; j < 4; j++) acc2[i][j] = 0ULL;

    #pragma unroll 1
    for (int k0 = 0; k0 < KTOT; k0 += BK) {
        #pragma unroll
        for (int it = 0; it < 4; ++it) {           // A: 128 rows x 32 k
            int idx = it * 256 + tid;
            int r = idx >> 3, kq = idx & 7;
            float4 v = *reinterpret_cast<const float4*>(&A[(size_t)(m0 + r) * LD + k0 + kq * 4]);
            *reinterpret_cast<float4*>(&As[r * PAD_W + kq * 4]) = v;
        }
        #pragma unroll
        for (int it = 0; it < 2; ++it) {           // B: 64 rows x 32 k
            int idx = it * 256 + tid;
            int r = idx >> 3, kq = idx & 7;
            float4 v = *reinterpret_cast<const float4*>(&B[(size_t)(n0 + r) * LD + k0 + kq * 4]);
            *reinterpret_cast<float4*>(&Bs[r * PAD_W + kq * 4]) = v;
        }
        __syncthreads();

        #pragma unroll
        for (int k4 = 0; k4 < BK; k4 += 4) {
            ulonglong2 ap[8];
            #pragma unroll
            for (int i = 0; i < 8; i++)
                ap[i] = *reinterpret_cast<const ulonglong2*>(&As[(tr * 8 + i) * PAD_W + k4]);
            ulonglong2 bp[4];
            #pragma unroll
            for (int j = 0; j < 4; j++)
                bp[j] = *reinterpret_cast<const ulonglong2*>(&Bs[(tc + 16 * j) * PAD_W + k4]);
            #pragma unroll
            for (int i = 0; i < 8; i++)
                #pragma unroll
                for (int j = 0; j < 4; j++) {
                    asm("fma.rn.f32x2 %0, %1, %2, %0;" : "+l"(acc2[i][j]) : "l"(ap[i].x), "l"(bp[j].x));
                    asm("fma.rn.f32x2 %0, %1, %2, %0;" : "+l"(acc2[i][j]) : "l"(ap[i].y), "l"(bp[j].y));
                }
        }
        __syncthreads();
    }

    float* C = Cg + bz * strC;
    #pragma unroll
    for (int i = 0; i < 8; i++) {
        int m = m0 + tr * 8 + i;
        #pragma unroll
        for (int j = 0; j < 4; j++) {
            float lo, hi;
            asm("mov.b64 {%0, %1}, %2;" : "=f"(lo), "=f"(hi) : "l"(acc2[i][j]));
            C[(size_t)m * ldc + n0 + tc + 16 * j] = lo + hi;
        }
    }
}

// ===========================================================================
// Checkers: sampled verification vs fp32 warp dot-products (gated fixups).
// ===========================================================================
__global__ void __launch_bounds__(256) check_S() {
    int wid = threadIdx.x >> 5, lane = threadIdx.x & 31;
    int s = blockIdx.x * 8 + wid;
    uint32_t u = (uint32_t)s * 2654435761u;
    int b = s & 3;
    int i = (u >> 8) & 4095;
    int j = (u >> 20) & 4095;
    const float* q = g_qT + (size_t)b * STR_CN;   // [i][c]
    const float* k = g_kT + (size_t)b * STR_CN;
    float acc = 0.f;
    #pragma unroll
    for (int c = lane; c < 256; c += 32)
        acc = fmaf(q[(size_t)i * NC + c], k[(size_t)j * NC + c], acc);
    #pragma unroll
    for (int o = 16; o; o >>= 1) acc += __shfl_xor_sync(0xffffffffu, acc, o);
    if (lane == 0) {
        float got = g_S[(size_t)b * STR_NN + (size_t)i * NN + j];
        if (fabsf(got - acc) > 1e-2f * fmaxf(fabsf(acc), 1.0f))
            atomicAdd(&g_flags[0], 1);
    }
}

__global__ void __launch_bounds__(256) check_AV() {
    int wid = threadIdx.x >> 5, lane = threadIdx.x & 31;
    int s = blockIdx.x * 8 + wid;
    uint32_t u = (uint32_t)s * 2654435761u;
    int b = s & 3;
    int c = (u >> 8) & 255;
    int i = (u >> 20) & 4095;
    const float* v = g_v + (size_t)b * STR_CN + (size_t)c * NN;
    const float* P = g_S + (size_t)b * STR_NN + (size_t)i * NN;
    float acc = 0.f;
    #pragma unroll 4
    for (int j = lane; j < 4096; j += 32)
        acc = fmaf(v[j], P[j], acc);
    #pragma unroll
    for (int o = 16; o; o >>= 1) acc += __shfl_xor_sync(0xffffffffu, acc, o);
    if (lane == 0) {
        float got = g_o[(size_t)b * STR_CN + (size_t)c * NN + i];
        if (fabsf(got - acc) > 1e-2f * fmaxf(fabsf(acc), 1.0f))
            atomicAdd(&g_flags[1], 1);
    }
}

// ===========================================================================
// Softmax (round-1 proven), in place on g_S
// ===========================================================================
__global__ void __launch_bounds__(256) softmax_kernel() {
    size_t row = blockIdx.x;
    float* p = g_S + row * NN;
    int tid = threadIdx.x;
    int lane = tid & 31, wid = tid >> 5;
    __shared__ float red[8];
    __shared__ float sh_bcast;

    float4 v[4];
    float mx = -INFINITY;
    #pragma unroll
    for (int i = 0; i < 4; i++) {
        v[i] = reinterpret_cast<float4*>(p)[tid + i * 256];
        mx = fmaxf(mx, fmaxf(fmaxf(v[i].x, v[i].y), fmaxf(v[i].z, v[i].w)));
    }
    #pragma unroll
    for (int o = 16; o; o >>= 1) mx = fmaxf(mx, __shfl_xor_sync(0xffffffffu, mx, o));
    if (lane == 0) red[wid] = mx;
    __syncthreads();
    if (tid == 0) {
        float m = red[0];
        #pragma unroll
        for (int i = 1; i < 8; i++) m = fmaxf(m, red[i]);
        sh_bcast = m;
    }
    __syncthreads();
    mx = sh_bcast;
    __syncthreads();

    float sum = 0.f;
    #pragma unroll
    for (int i = 0; i < 4; i++) {
        v[i].x = __expf(v[i].x - mx); v[i].y = __expf(v[i].y - mx);
        v[i].z = __expf(v[i].z - mx); v[i].w = __expf(v[i].w - mx);
        sum += v[i].x + v[i].y + v[i].z + v[i].w;
    }
    #pragma unroll
    for (int o = 16; o; o >>= 1) sum += __shfl_xor_sync(0xffffffffu, sum, o);
    if (lane == 0) red[wid] = sum;
    __syncthreads();
    if (tid == 0) {
        float s = 0.f;
        #pragma unroll
        for (int i = 0; i < 8; i++) s += red[i];
        sh_bcast = 1.0f / s;
    }
    __syncthreads();
    float inv = sh_bcast;

    #pragma unroll
    for (int i = 0; i < 4; i++) {
        v[i].x *= inv; v[i].y *= inv; v[i].z *= inv; v[i].w *= inv;
        reinterpret_cast<float4*>(p)[tid + i * 256] = v[i];
    }
}

// ===========================================================================
extern "C" void kernel_launch(void* const* d_in, const int* in_sizes, int n_in,
                              void* d_out, int out_size) {
    const float* x      = (const float*)d_in[0];
    const float* norm_w = (const float*)d_in[1];
    const float* norm_b = (const float*)d_in[2];
    const float* qkv_w  = (const float*)d_in[3];
    const float* qkv_b  = (const float*)d_in[4];
    const float* proj_w = (const float*)d_in[5];
    const float* proj_b = (const float*)d_in[6];
    float* out = (float*)d_out;

    init_flags<<<1, 1>>>();

    // 1-2. GroupNorm + QKV (fp32, proven) -> q^T,k^T [i][c] and v [c][i]
    gn_kernel<<<NB * NGRP, 256>>>(x, norm_w, norm_b);
    gemm_kernel<OP_QKV><<<dim3(NN / 64, 768 / 128, NB), 256>>>(qkv_w, qkv_b, nullptr, nullptr);

    // 3. S = Q^T K via k-SIMD f32x2; verify; gated fp32 fixup
    gemm2k_kernel<256, 256><<<dim3(NN / 64, NN / 128, NB), 256>>>(
        g_qT, g_kT, g_S, STR_CN, STR_CN, STR_NN, NN);
    check_S<<<256, 256>>>();
    gemm_kernel<OP_S><<<dim3(NN / 64, NN / 128, NB), 256>>>(nullptr, nullptr, nullptr, nullptr);

    // 4. softmax (fp32, proven)
    softmax_kernel<<<NB * NN, 256>>>();

    // 5. O = V P^T via k-SIMD f32x2; verify; gated fp32 fixup
    gemm2k_kernel<4096, 4096><<<dim3(NN / 64, NC / 128, NB), 256>>>(
        g_v, g_S, g_o, STR_CN, STR_NN, STR_CN, NN);
    check_AV<<<256, 256>>>();
    gemm_kernel<OP_AV><<<dim3(NN / 64, NC / 128, NB), 256>>>(nullptr, nullptr, nullptr, nullptr);

    // 6. proj + bias + residual (fp32, proven)
    gemm_kernel<OP_PROJ><<<dim3(NN / 64, NC / 128, NB), 256>>>(proj_w, proj_b, x, out);
}

// round 12
// speedup vs baseline: 11.5513x; 11.5513x over previous
#include <cuda_runtime.h>
#include <cstdint>
#include <math.h>

// Problem constants: B=4, C=256, H=W=64 -> N=4096, num_heads=1, d=256
#define NB    4
#define NC    256
#define NN    4096
#define NGRP  32

static __device__ float g_xn[NB * NC * NN];
static __device__ float g_q [NB * NC * NN];   // [b][c][i], q pre-scaled by d^-0.5
static __device__ float g_k [NB * NC * NN];
static __device__ float g_v [NB * NC * NN];
static __device__ float g_o [NB * NC * NN];
static __device__ float g_S [(size_t)NB * NN * NN];   // 256 MB scores / probs

// flags: [0] = bad-S sample count, [1] = bad-AV sample count
static __device__ int g_flags[2];

static constexpr size_t STR_CN = (size_t)NC * NN;     // 1048576
static constexpr size_t STR_NN = (size_t)NN * NN;     // 16777216

__global__ void init_flags() { g_flags[0] = 0; g_flags[1] = 0; }

// ===========================================================================
// GroupNorm (round-1 proven)
// ===========================================================================
__global__ void __launch_bounds__(256) gn_kernel(const float* __restrict__ x,
                                                 const float* __restrict__ w,
                                                 const float* __restrict__ b) {
    int batch = blockIdx.x >> 5;
    int grp   = blockIdx.x & 31;
    const float* xp = x    + ((size_t)batch * NC + grp * 8) * NN;
    float*       op = g_xn + ((size_t)batch * NC + grp * 8) * NN;
    int tid = threadIdx.x;

    float s = 0.f, s2 = 0.f;
    #pragma unroll 4
    for (int i = tid; i < 8192; i += 256) {
        float4 t = reinterpret_cast<const float4*>(xp)[i];
        s  += t.x + t.y + t.z + t.w;
        s2 += t.x * t.x + t.y * t.y + t.z * t.z + t.w * t.w;
    }
    __shared__ float rs[8], rs2[8];
    __shared__ float sh_mean, sh_rstd;
    int lane = tid & 31, wid = tid >> 5;
    #pragma unroll
    for (int o = 16; o; o >>= 1) {
        s  += __shfl_xor_sync(0xffffffffu, s,  o);
        s2 += __shfl_xor_sync(0xffffffffu, s2, o);
    }
    if (lane == 0) { rs[wid] = s; rs2[wid] = s2; }
    __syncthreads();
    if (tid == 0) {
        float ts = 0.f, ts2 = 0.f;
        #pragma unroll
        for (int i = 0; i < 8; i++) { ts += rs[i]; ts2 += rs2[i]; }
        float mean = ts * (1.0f / 32768.0f);
        float var  = ts2 * (1.0f / 32768.0f) - mean * mean;
        sh_mean = mean;
        sh_rstd = rsqrtf(var + 1e-5f);
    }
    __syncthreads();
    float mean = sh_mean, rstd = sh_rstd;

    #pragma unroll 4
    for (int i = tid; i < 8192; i += 256) {
        int c = grp * 8 + (i >> 10);
        float sc = rstd * w[c];
        float shf = b[c] - mean * sc;
        float4 t = reinterpret_cast<const float4*>(xp)[i];
        t.x = t.x * sc + shf; t.y = t.y * sc + shf;
        t.z = t.z * sc + shf; t.w = t.w * sc + shf;
        reinterpret_cast<float4*>(op)[i] = t;
    }
}

// ===========================================================================
// fp32 tiled GEMM (round-1 proven). OP_S / OP_AV variants are gated fixups
// that only execute when the f32x2 result failed verification.
// ===========================================================================
#define OP_QKV  0
#define OP_S    1
#define OP_AV   2
#define OP_PROJ 3

template <int OP>
__global__ void __launch_bounds__(256) gemm_kernel(const float* __restrict__ extA,
                                                   const float* __restrict__ bias,
                                                   const float* __restrict__ resid,
                                                   float* __restrict__ extOut) {
    if constexpr (OP == OP_S)  { if (g_flags[0] == 0) return; }
    if constexpr (OP == OP_AV) { if (g_flags[1] == 0) return; }

    constexpr int BM = 128, BN = 64, BK = 32;
    constexpr int K   = (OP == OP_AV) ? 4096 : 256;
    constexpr bool A_T = (OP == OP_QKV || OP == OP_AV || OP == OP_PROJ);
    constexpr bool B_T = (OP == OP_AV);
    constexpr int LDA = (OP == OP_QKV || OP == OP_PROJ) ? 256 : 4096;
    constexpr int LDB = 4096;

    __shared__ float As[BK][BM + 4];
    __shared__ float Bs[BK][BN + 4];

    size_t bz = blockIdx.z;
    const float* A;
    const float* B;
    if constexpr (OP == OP_QKV)      { A = extA;              B = g_xn + bz * STR_CN; }
    else if constexpr (OP == OP_S)   { A = g_q + bz * STR_CN; B = g_k  + bz * STR_CN; }
    else if constexpr (OP == OP_AV)  { A = g_v + bz * STR_CN; B = g_S  + bz * STR_NN; }
    else                             { A = extA;              B = g_o  + bz * STR_CN; }

    int m0 = blockIdx.y * BM;
    int n0 = blockIdx.x * BN;
    int tid = threadIdx.x;
    int tr = tid >> 4;
    int tc = tid & 15;

    float acc[8][4];
    #pragma unroll
    for (int i = 0; i < 8; i++)
        #pragma unroll
        for (int j = 0; j < 4; j++) acc[i][j] = 0.f;

    #pragma unroll 1
    for (int k0 = 0; k0 < K; k0 += BK) {
        if constexpr (A_T) {
            int m = tid >> 3, kq = tid & 7;
            #pragma unroll
            for (int it = 0; it < 4; ++it, m += 32) {
                float4 va = *reinterpret_cast<const float4*>(&A[(size_t)(m0 + m) * LDA + k0 + kq * 4]);
                As[kq * 4 + 0][m] = va.x;
                As[kq * 4 + 1][m] = va.y;
                As[kq * 4 + 2][m] = va.z;
                As[kq * 4 + 3][m] = va.w;
            }
        } else {
            int kk = tid >> 5, m4 = tid & 31;
            #pragma unroll
            for (int it = 0; it < 4; ++it, kk += 8) {
                float4 va = *reinterpret_cast<const float4*>(&A[(size_t)(k0 + kk) * LDA + m0 + m4 * 4]);
                *reinterpret_cast<float4*>(&As[kk][m4 * 4]) = va;
            }
        }
        if constexpr (B_T) {
            int n = tid >> 3, kq = tid & 7;
            #pragma unroll
            for (int it = 0; it < 2; ++it, n += 32) {
                float4 vb = *reinterpret_cast<const float4*>(&B[(size_t)(n0 + n) * LDB + k0 + kq * 4]);
                Bs[kq * 4 + 0][n] = vb.x;
                Bs[kq * 4 + 1][n] = vb.y;
                Bs[kq * 4 + 2][n] = vb.z;
                Bs[kq * 4 + 3][n] = vb.w;
            }
        } else {
            int kk = tid >> 4, n4 = tid & 15;
            #pragma unroll
            for (int it = 0; it < 2; ++it, kk += 16) {
                float4 vb = *reinterpret_cast<const float4*>(&B[(size_t)(k0 + kk) * LDB + n0 + n4 * 4]);
                *reinterpret_cast<float4*>(&Bs[kk][n4 * 4]) = vb;
            }
        }
        __syncthreads();

        #pragma unroll
        for (int kk = 0; kk < BK; ++kk) {
            float4 a0 = *reinterpret_cast<const float4*>(&As[kk][tr * 8]);
            float4 a1 = *reinterpret_cast<const float4*>(&As[kk][tr * 8 + 4]);
            float4 b0 = *reinterpret_cast<const float4*>(&Bs[kk][tc * 4]);
            float av[8] = {a0.x, a0.y, a0.z, a0.w, a1.x, a1.y, a1.z, a1.w};
            float bv[4] = {b0.x, b0.y, b0.z, b0.w};
            #pragma unroll
            for (int i = 0; i < 8; i++)
                #pragma unroll
                for (int j = 0; j < 4; j++)
                    acc[i][j] = fmaf(av[i], bv[j], acc[i][j]);
        }
        __syncthreads();
    }

    int nbase = n0 + tc * 4;
    #pragma unroll
    for (int i = 0; i < 8; i++) {
        int m = m0 + tr * 8 + i;
        float4 r = make_float4(acc[i][0], acc[i][1], acc[i][2], acc[i][3]);
        if constexpr (OP == OP_QKV) {
            float bv = bias[m];
            r.x += bv; r.y += bv; r.z += bv; r.w += bv;
            size_t off = bz * STR_CN + (size_t)(m & 255) * NN + nbase;
            if (m < 256) {
                r.x *= 0.0625f; r.y *= 0.0625f; r.z *= 0.0625f; r.w *= 0.0625f;
                *reinterpret_cast<float4*>(&g_q[off]) = r;
            } else if (m < 512) {
                *reinterpret_cast<float4*>(&g_k[off]) = r;
            } else {
                *reinterpret_cast<float4*>(&g_v[off]) = r;
            }
        } else if constexpr (OP == OP_S) {
            *reinterpret_cast<float4*>(&g_S[bz * STR_NN + (size_t)m * NN + nbase]) = r;
        } else if constexpr (OP == OP_AV) {
            *reinterpret_cast<float4*>(&g_o[bz * STR_CN + (size_t)m * NN + nbase]) = r;
        } else {
            float bv = bias[m];
            size_t off = bz * STR_CN + (size_t)m * NN + nbase;
            float4 xr = *reinterpret_cast<const float4*>(&resid[off]);
            r.x += bv + xr.x; r.y += bv + xr.y; r.z += bv + xr.z; r.w += bv + xr.w;
            *reinterpret_cast<float4*>(&extOut[off]) = r;
        }
    }
}

// ===========================================================================
// f32x2 packed GEMM for S and AV (R10 skeleton, row-pair FFMA2 lanes):
// lanes carry adjacent m rows, whose operands are already contiguous in
// As[kk][m] -> reinterpret the A row-slice as 4 x u64 (zero packing movs).
// Only B needs lane duplication (4 movs/kk). Per-lane k-order identical to
// the scalar fp32 kernel -> bitwise-identical results.
// ===========================================================================
template <int OP>
__global__ void __launch_bounds__(256) gemm2_kernel() {
    constexpr int BM = 128, BN = 64, BK = 32;
    constexpr int K   = (OP == OP_AV) ? 4096 : 256;
    constexpr bool A_T = (OP == OP_AV);
    constexpr bool B_T = (OP == OP_AV);
    constexpr int LDA = 4096;
    constexpr int LDB = 4096;

    __shared__ float As[BK][BM + 4];
    __shared__ float Bs[BK][BN + 4];

    size_t bz = blockIdx.z;
    const float* A;
    const float* B;
    if constexpr (OP == OP_S) { A = g_q + bz * STR_CN; B = g_k + bz * STR_CN; }
    else                      { A = g_v + bz * STR_CN; B = g_S + bz * STR_NN; }

    int m0 = blockIdx.y * BM;
    int n0 = blockIdx.x * BN;
    int tid = threadIdx.x;
    int tr = tid >> 4;
    int tc = tid & 15;

    // acc2[ip][j]: lane0 = row tr*8 + 2*ip, lane1 = row tr*8 + 2*ip + 1, col j
    unsigned long long acc2[4][4];
    #pragma unroll
    for (int i = 0; i < 4; i++)
        #pragma unroll
        for (int j = 0; j < 4; j++) acc2[i][j] = 0ULL;

    #pragma unroll 1
    for (int k0 = 0; k0 < K; k0 += BK) {
        if constexpr (A_T) {
            int m = tid >> 3, kq = tid & 7;
            #pragma unroll
            for (int it = 0; it < 4; ++it, m += 32) {
                float4 va = *reinterpret_cast<const float4*>(&A[(size_t)(m0 + m) * LDA + k0 + kq * 4]);
                As[kq * 4 + 0][m] = va.x;
                As[kq * 4 + 1][m] = va.y;
                As[kq * 4 + 2][m] = va.z;
                As[kq * 4 + 3][m] = va.w;
            }
        } else {
            int kk = tid >> 5, m4 = tid & 31;
            #pragma unroll
            for (int it = 0; it < 4; ++it, kk += 8) {
                float4 va = *reinterpret_cast<const float4*>(&A[(size_t)(k0 + kk) * LDA + m0 + m4 * 4]);
                *reinterpret_cast<float4*>(&As[kk][m4 * 4]) = va;
            }
        }
        if constexpr (B_T) {
            int n = tid >> 3, kq = tid & 7;
            #pragma unroll
            for (int it = 0; it < 2; ++it, n += 32) {
                float4 vb = *reinterpret_cast<const float4*>(&B[(size_t)(n0 + n) * LDB + k0 + kq * 4]);
                Bs[kq * 4 + 0][n] = vb.x;
                Bs[kq * 4 + 1][n] = vb.y;
                Bs[kq * 4 + 2][n] = vb.z;
                Bs[kq * 4 + 3][n] = vb.w;
            }
        } else {
            int kk = tid >> 4, n4 = tid & 15;
            #pragma unroll
            for (int it = 0; it < 2; ++it, kk += 16) {
                float4 vb = *reinterpret_cast<const float4*>(&B[(size_t)(k0 + kk) * LDB + n0 + n4 * 4]);
                *reinterpret_cast<float4*>(&Bs[kk][n4 * 4]) = vb;
            }
        }
        __syncthreads();

        #pragma unroll
        for (int kk = 0; kk < BK; ++kk) {
            // A rows tr*8 .. tr*8+7 at this k: 8 consecutive floats = 4 u64 pairs
            float4 a0 = *reinterpret_cast<const float4*>(&As[kk][tr * 8]);
            float4 a1 = *reinterpret_cast<const float4*>(&As[kk][tr * 8 + 4]);
            unsigned long long ap[4];
            asm("mov.b64 %0, {%1, %2};" : "=l"(ap[0]) : "f"(a0.x), "f"(a0.y));
            asm("mov.b64 %0, {%1, %2};" : "=l"(ap[1]) : "f"(a0.z), "f"(a0.w));
            asm("mov.b64 %0, {%1, %2};" : "=l"(ap[2]) : "f"(a1.x), "f"(a1.y));
            asm("mov.b64 %0, {%1, %2};" : "=l"(ap[3]) : "f"(a1.z), "f"(a1.w));
            float4 b0 = *reinterpret_cast<const float4*>(&Bs[kk][tc * 4]);
            unsigned long long bd[4];
            asm("mov.b64 %0, {%1, %1};" : "=l"(bd[0]) : "f"(b0.x));
            asm("mov.b64 %0, {%1, %1};" : "=l"(bd[1]) : "f"(b0.y));
            asm("mov.b64 %0, {%1, %1};" : "=l"(bd[2]) : "f"(b0.z));
            asm("mov.b64 %0, {%1, %1};" : "=l"(bd[3]) : "f"(b0.w));
            #pragma unroll
            for (int ip = 0; ip < 4; ip++)
                #pragma unroll
                for (int j = 0; j < 4; j++)
                    asm("fma.rn.f32x2 %0, %1, %2, %0;"
                        : "+l"(acc2[ip][j]) : "l"(ap[ip]), "l"(bd[j]));
        }
        __syncthreads();
    }

    int nbase = n0 + tc * 4;
    #pragma unroll
    for (int ip = 0; ip < 4; ip++) {
        float lo[4], hi[4];
        #pragma unroll
        for (int j = 0; j < 4; j++)
            asm("mov.b64 {%0, %1}, %2;" : "=f"(lo[j]), "=f"(hi[j]) : "l"(acc2[ip][j]));
        int m = m0 + tr * 8 + ip * 2;
        float4 r0 = make_float4(lo[0], lo[1], lo[2], lo[3]);
        float4 r1 = make_float4(hi[0], hi[1], hi[2], hi[3]);
        if constexpr (OP == OP_S) {
            *reinterpret_cast<float4*>(&g_S[bz * STR_NN + (size_t)m * NN + nbase])       = r0;
            *reinterpret_cast<float4*>(&g_S[bz * STR_NN + (size_t)(m + 1) * NN + nbase]) = r1;
        } else {
            *reinterpret_cast<float4*>(&g_o[bz * STR_CN + (size_t)m * NN + nbase])       = r0;
            *reinterpret_cast<float4*>(&g_o[bz * STR_CN + (size_t)(m + 1) * NN + nbase]) = r1;
        }
    }
}

// ===========================================================================
// Checkers (proven): sampled verification vs fp32 warp dot-products.
// ===========================================================================
__global__ void __launch_bounds__(256) check_S() {
    int wid = threadIdx.x >> 5, lane = threadIdx.x & 31;
    int s = blockIdx.x * 8 + wid;
    uint32_t u = (uint32_t)s * 2654435761u;
    int b = s & 3;
    int i = (u >> 8) & 4095;
    int j = (u >> 20) & 4095;
    const float* q = g_q + (size_t)b * STR_CN;
    const float* k = g_k + (size_t)b * STR_CN;
    float acc = 0.f;
    #pragma unroll
    for (int c = lane; c < 256; c += 32)
        acc = fmaf(q[(size_t)c * NN + i], k[(size_t)c * NN + j], acc);
    #pragma unroll
    for (int o = 16; o; o >>= 1) acc += __shfl_xor_sync(0xffffffffu, acc, o);
    if (lane == 0) {
        float got = g_S[(size_t)b * STR_NN + (size_t)i * NN + j];
        if (fabsf(got - acc) > 1e-2f * fmaxf(fabsf(acc), 1.0f))
            atomicAdd(&g_flags[0], 1);
    }
}

__global__ void __launch_bounds__(256) check_AV() {
    int wid = threadIdx.x >> 5, lane = threadIdx.x & 31;
    int s = blockIdx.x * 8 + wid;
    uint32_t u = (uint32_t)s * 2654435761u;
    int b = s & 3;
    int c = (u >> 8) & 255;
    int i = (u >> 20) & 4095;
    const float* v = g_v + (size_t)b * STR_CN + (size_t)c * NN;
    const float* P = g_S + (size_t)b * STR_NN + (size_t)i * NN;
    float acc = 0.f;
    #pragma unroll 4
    for (int j = lane; j < 4096; j += 32)
        acc = fmaf(v[j], P[j], acc);
    #pragma unroll
    for (int o = 16; o; o >>= 1) acc += __shfl_xor_sync(0xffffffffu, acc, o);
    if (lane == 0) {
        float got = g_o[(size_t)b * STR_CN + (size_t)c * NN + i];
        if (fabsf(got - acc) > 1e-2f * fmaxf(fabsf(acc), 1.0f))
            atomicAdd(&g_flags[1], 1);
    }
}

// ===========================================================================
// Softmax (round-1 proven), in place on g_S
// ===========================================================================
__global__ void __launch_bounds__(256) softmax_kernel() {
    size_t row = blockIdx.x;
    float* p = g_S + row * NN;
    int tid = threadIdx.x;
    int lane = tid & 31, wid = tid >> 5;
    __shared__ float red[8];
    __shared__ float sh_bcast;

    float4 v[4];
    float mx = -INFINITY;
    #pragma unroll
    for (int i = 0; i < 4; i++) {
        v[i] = reinterpret_cast<float4*>(p)[tid + i * 256];
        mx = fmaxf(mx, fmaxf(fmaxf(v[i].x, v[i].y), fmaxf(v[i].z, v[i].w)));
    }
    #pragma unroll
    for (int o = 16; o; o >>= 1) mx = fmaxf(mx, __shfl_xor_sync(0xffffffffu, mx, o));
    if (lane == 0) red[wid] = mx;
    __syncthreads();
    if (tid == 0) {
        float m = red[0];
        #pragma unroll
        for (int i = 1; i < 8; i++) m = fmaxf(m, red[i]);
        sh_bcast = m;
    }
    __syncthreads();
    mx = sh_bcast;
    __syncthreads();

    float sum = 0.f;
    #pragma unroll
    for (int i = 0; i < 4; i++) {
        v[i].x = __expf(v[i].x - mx); v[i].y = __expf(v[i].y - mx);
        v[i].z = __expf(v[i].z - mx); v[i].w = __expf(v[i].w - mx);
        sum += v[i].x + v[i].y + v[i].z + v[i].w;
    }
    #pragma unroll
    for (int o = 16; o; o >>= 1) sum += __shfl_xor_sync(0xffffffffu, sum, o);
    if (lane == 0) red[wid] = sum;
    __syncthreads();
    if (tid == 0) {
        float s = 0.f;
        #pragma unroll
        for (int i = 0; i < 8; i++) s += red[i];
        sh_bcast = 1.0f / s;
    }
    __syncthreads();
    float inv = sh_bcast;

    #pragma unroll
    for (int i = 0; i < 4; i++) {
        v[i].x *= inv; v[i].y *= inv; v[i].z *= inv; v[i].w *= inv;
        reinterpret_cast<float4*>(p)[tid + i * 256] = v[i];
    }
}

// ===========================================================================
extern "C" void kernel_launch(void* const* d_in, const int* in_sizes, int n_in,
                              void* d_out, int out_size) {
    const float* x      = (const float*)d_in[0];
    const float* norm_w = (const float*)d_in[1];
    const float* norm_b = (const float*)d_in[2];
    const float* qkv_w  = (const float*)d_in[3];
    const float* qkv_b  = (const float*)d_in[4];
    const float* proj_w = (const float*)d_in[5];
    const float* proj_b = (const float*)d_in[6];
    float* out = (float*)d_out;

    init_flags<<<1, 1>>>();

    // 1-2. GroupNorm + QKV (fp32, proven)
    gn_kernel<<<NB * NGRP, 256>>>(x, norm_w, norm_b);
    gemm_kernel<OP_QKV><<<dim3(NN / 64, 768 / 128, NB), 256>>>(qkv_w, qkv_b, nullptr, nullptr);

    // 3. S = Q^T K via f32x2 row-pair; verify; gated fp32 fixup
    gemm2_kernel<OP_S><<<dim3(NN / 64, NN / 128, NB), 256>>>();
    check_S<<<256, 256>>>();
    gemm_kernel<OP_S><<<dim3(NN / 64, NN / 128, NB), 256>>>(nullptr, nullptr, nullptr, nullptr);

    // 4. softmax (fp32, proven)
    softmax_kernel<<<NB * NN, 256>>>();

    // 5. O = V P^T via f32x2 row-pair; verify; gated fp32 fixup
    gemm2_kernel<OP_AV><<<dim3(NN / 64, NC / 128, NB), 256>>>();
    check_AV<<<256, 256>>>();
    gemm_kernel<OP_AV><<<dim3(NN / 64, NC / 128, NB), 256>>>(nullptr, nullptr, nullptr, nullptr);

    // 6. proj + bias + residual (fp32, proven)
    gemm_kernel<OP_PROJ><<<dim3(NN / 64, NC / 128, NB), 256>>>(proj_w, proj_b, x, out);
}

// round 13
// speedup vs baseline: 12.5219x; 1.0840x over previous
#include <cuda_runtime.h>
#include <cstdint>
#include <math.h>

// Problem constants: B=4, C=256, H=W=64 -> N=4096, num_heads=1, d=256
#define NB    4
#define NC    256
#define NN    4096
#define NGRP  32

static __device__ float g_xn[NB * NC * NN];
static __device__ float g_q [NB * NC * NN];   // [b][c][i], q pre-scaled by d^-0.5
static __device__ float g_k [NB * NC * NN];
static __device__ float g_v [NB * NC * NN];
static __device__ float g_o [NB * NC * NN];
static __device__ float g_S [(size_t)NB * NN * NN];   // 256 MB scores / probs

static constexpr size_t STR_CN = (size_t)NC * NN;     // 1048576
static constexpr size_t STR_NN = (size_t)NN * NN;     // 16777216

// ===========================================================================
// GroupNorm (round-1 proven)
// ===========================================================================
__global__ void __launch_bounds__(256) gn_kernel(const float* __restrict__ x,
                                                 const float* __restrict__ w,
                                                 const float* __restrict__ b) {
    int batch = blockIdx.x >> 5;
    int grp   = blockIdx.x & 31;
    const float* xp = x    + ((size_t)batch * NC + grp * 8) * NN;
    float*       op = g_xn + ((size_t)batch * NC + grp * 8) * NN;
    int tid = threadIdx.x;

    float s = 0.f, s2 = 0.f;
    #pragma unroll 4
    for (int i = tid; i < 8192; i += 256) {
        float4 t = reinterpret_cast<const float4*>(xp)[i];
        s  += t.x + t.y + t.z + t.w;
        s2 += t.x * t.x + t.y * t.y + t.z * t.z + t.w * t.w;
    }
    __shared__ float rs[8], rs2[8];
    __shared__ float sh_mean, sh_rstd;
    int lane = tid & 31, wid = tid >> 5;
    #pragma unroll
    for (int o = 16; o; o >>= 1) {
        s  += __shfl_xor_sync(0xffffffffu, s,  o);
        s2 += __shfl_xor_sync(0xffffffffu, s2, o);
    }
    if (lane == 0) { rs[wid] = s; rs2[wid] = s2; }
    __syncthreads();
    if (tid == 0) {
        float ts = 0.f, ts2 = 0.f;
        #pragma unroll
        for (int i = 0; i < 8; i++) { ts += rs[i]; ts2 += rs2[i]; }
        float mean = ts * (1.0f / 32768.0f);
        float var  = ts2 * (1.0f / 32768.0f) - mean * mean;
        sh_mean = mean;
        sh_rstd = rsqrtf(var + 1e-5f);
    }
    __syncthreads();
    float mean = sh_mean, rstd = sh_rstd;

    #pragma unroll 4
    for (int i = tid; i < 8192; i += 256) {
        int c = grp * 8 + (i >> 10);
        float sc = rstd * w[c];
        float shf = b[c] - mean * sc;
        float4 t = reinterpret_cast<const float4*>(xp)[i];
        t.x = t.x * sc + shf; t.y = t.y * sc + shf;
        t.z = t.z * sc + shf; t.w = t.w * sc + shf;
        reinterpret_cast<float4*>(op)[i] = t;
    }
}

// ===========================================================================
// Staging helpers (global -> regs -> smem), layouts identical to round-1.
// ===========================================================================
template <bool A_T, int LDA>
__device__ __forceinline__ void stageA(float4 (&pa)[4], const float* __restrict__ A,
                                       int m0, int k0, int tid) {
    if constexpr (A_T) {
        int m = tid >> 3, kq = tid & 7;
        #pragma unroll
        for (int it = 0; it < 4; ++it)
            pa[it] = *reinterpret_cast<const float4*>(&A[(size_t)(m0 + m + 32 * it) * LDA + k0 + kq * 4]);
    } else {
        int kk = tid >> 5, m4 = tid & 31;
        #pragma unroll
        for (int it = 0; it < 4; ++it)
            pa[it] = *reinterpret_cast<const float4*>(&A[(size_t)(k0 + kk + 8 * it) * LDA + m0 + m4 * 4]);
    }
}
template <bool A_T>
__device__ __forceinline__ void commitA(float (*As)[132], const float4 (&pa)[4], int tid) {
    if constexpr (A_T) {
        int m = tid >> 3, kq = tid & 7;
        #pragma unroll
        for (int it = 0; it < 4; ++it) {
            As[kq * 4 + 0][m + 32 * it] = pa[it].x;
            As[kq * 4 + 1][m + 32 * it] = pa[it].y;
            As[kq * 4 + 2][m + 32 * it] = pa[it].z;
            As[kq * 4 + 3][m + 32 * it] = pa[it].w;
        }
    } else {
        int kk = tid >> 5, m4 = tid & 31;
        #pragma unroll
        for (int it = 0; it < 4; ++it)
            *reinterpret_cast<float4*>(&As[kk + 8 * it][m4 * 4]) = pa[it];
    }
}
template <bool B_T, int LDB>
__device__ __forceinline__ void stageB(float4 (&pb)[2], const float* __restrict__ B,
                                       int n0, int k0, int tid) {
    if constexpr (B_T) {
        int n = tid >> 3, kq = tid & 7;
        #pragma unroll
        for (int it = 0; it < 2; ++it)
            pb[it] = *reinterpret_cast<const float4*>(&B[(size_t)(n0 + n + 32 * it) * LDB + k0 + kq * 4]);
    } else {
        int kk = tid >> 4, n4 = tid & 15;
        #pragma unroll
        for (int it = 0; it < 2; ++it)
            pb[it] = *reinterpret_cast<const float4*>(&B[(size_t)(k0 + kk + 16 * it) * LDB + n0 + n4 * 4]);
    }
}
template <bool B_T>
__device__ __forceinline__ void commitB(float (*Bs)[68], const float4 (&pb)[2], int tid) {
    if constexpr (B_T) {
        int n = tid >> 3, kq = tid & 7;
        #pragma unroll
        for (int it = 0; it < 2; ++it) {
            Bs[kq * 4 + 0][n + 32 * it] = pb[it].x;
            Bs[kq * 4 + 1][n + 32 * it] = pb[it].y;
            Bs[kq * 4 + 2][n + 32 * it] = pb[it].z;
            Bs[kq * 4 + 3][n + 32 * it] = pb[it].w;
        }
    } else {
        int kk = tid >> 4, n4 = tid & 15;
        #pragma unroll
        for (int it = 0; it < 2; ++it)
            *reinterpret_cast<float4*>(&Bs[kk + 16 * it][n4 * 4]) = pb[it];
    }
}

// ===========================================================================
// Unified FFMA2 GEMM (all four ops). Row-pair f32x2 inner loop (R12 proven,
// bitwise-identical to scalar fp32), register-staged software pipeline,
// round-1 proven epilogues (acc2 unpacked to acc[8][4] first).
// ===========================================================================
#define OP_QKV  0
#define OP_S    1
#define OP_AV   2
#define OP_PROJ 3

template <int OP>
__global__ void __launch_bounds__(256) gemm2_kernel(const float* __restrict__ extA,
                                                    const float* __restrict__ bias,
                                                    const float* __restrict__ resid,
                                                    float* __restrict__ extOut) {
    constexpr int BM = 128, BN = 64, BK = 32;
    constexpr int K   = (OP == OP_AV) ? 4096 : 256;
    constexpr bool A_T = (OP == OP_QKV || OP == OP_AV || OP == OP_PROJ);
    constexpr bool B_T = (OP == OP_AV);
    constexpr int LDA = (OP == OP_QKV || OP == OP_PROJ) ? 256 : 4096;
    constexpr int LDB = 4096;

    __shared__ float As[BK][BM + 4];
    __shared__ float Bs[BK][BN + 4];

    size_t bz = blockIdx.z;
    const float* A;
    const float* B;
    if constexpr (OP == OP_QKV)      { A = extA;              B = g_xn + bz * STR_CN; }
    else if constexpr (OP == OP_S)   { A = g_q + bz * STR_CN; B = g_k  + bz * STR_CN; }
    else if constexpr (OP == OP_AV)  { A = g_v + bz * STR_CN; B = g_S  + bz * STR_NN; }
    else                             { A = extA;              B = g_o  + bz * STR_CN; }

    int m0 = blockIdx.y * BM;
    int n0 = blockIdx.x * BN;
    int tid = threadIdx.x;
    int tr = tid >> 4;
    int tc = tid & 15;

    // acc2[ip][j]: lane0 = row tr*8 + 2*ip, lane1 = row tr*8 + 2*ip + 1, col j
    unsigned long long acc2[4][4];
    #pragma unroll
    for (int i = 0; i < 4; i++)
        #pragma unroll
        for (int j = 0; j < 4; j++) acc2[i][j] = 0ULL;

    // Prologue: tile 0 straight to smem
    {
        float4 pa[4]; float4 pb[2];
        stageA<A_T, LDA>(pa, A, m0, 0, tid);
        stageB<B_T, LDB>(pb, B, n0, 0, tid);
        commitA<A_T>(As, pa, tid);
        commitB<B_T>(Bs, pb, tid);
    }
    __syncthreads();

    #pragma unroll 1
    for (int k0 = 0; k0 < K; k0 += BK) {
        float4 pa[4]; float4 pb[2];
        bool has_next = (k0 + BK) < K;
        if (has_next) {                    // LDG issued before compute: hidden
            stageA<A_T, LDA>(pa, A, m0, k0 + BK, tid);
            stageB<B_T, LDB>(pb, B, n0, k0 + BK, tid);
        }

        #pragma unroll
        for (int kk = 0; kk < BK; ++kk) {
            float4 a0 = *reinterpret_cast<const float4*>(&As[kk][tr * 8]);
            float4 a1 = *reinterpret_cast<const float4*>(&As[kk][tr * 8 + 4]);
            unsigned long long ap[4];
            asm("mov.b64 %0, {%1, %2};" : "=l"(ap[0]) : "f"(a0.x), "f"(a0.y));
            asm("mov.b64 %0, {%1, %2};" : "=l"(ap[1]) : "f"(a0.z), "f"(a0.w));
            asm("mov.b64 %0, {%1, %2};" : "=l"(ap[2]) : "f"(a1.x), "f"(a1.y));
            asm("mov.b64 %0, {%1, %2};" : "=l"(ap[3]) : "f"(a1.z), "f"(a1.w));
            float4 b0 = *reinterpret_cast<const float4*>(&Bs[kk][tc * 4]);
            unsigned long long bd[4];
            asm("mov.b64 %0, {%1, %1};" : "=l"(bd[0]) : "f"(b0.x));
            asm("mov.b64 %0, {%1, %1};" : "=l"(bd[1]) : "f"(b0.y));
            asm("mov.b64 %0, {%1, %1};" : "=l"(bd[2]) : "f"(b0.z));
            asm("mov.b64 %0, {%1, %1};" : "=l"(bd[3]) : "f"(b0.w));
            #pragma unroll
            for (int ip = 0; ip < 4; ip++)
                #pragma unroll
                for (int j = 0; j < 4; j++)
                    asm("fma.rn.f32x2 %0, %1, %2, %0;"
                        : "+l"(acc2[ip][j]) : "l"(ap[ip]), "l"(bd[j]));
        }

        if (has_next) {
            __syncthreads();               // all reads of current tile done
            commitA<A_T>(As, pa, tid);
            commitB<B_T>(Bs, pb, tid);
            __syncthreads();               // new tile visible
        }
    }

    // Unpack packed accumulators into the round-1 acc[8][4] shape
    float acc[8][4];
    #pragma unroll
    for (int ip = 0; ip < 4; ip++)
        #pragma unroll
        for (int j = 0; j < 4; j++)
            asm("mov.b64 {%0, %1}, %2;"
                : "=f"(acc[2 * ip][j]), "=f"(acc[2 * ip + 1][j]) : "l"(acc2[ip][j]));

    // ---- round-1 proven epilogues ----
    int nbase = n0 + tc * 4;
    #pragma unroll
    for (int i = 0; i < 8; i++) {
        int m = m0 + tr * 8 + i;
        float4 r = make_float4(acc[i][0], acc[i][1], acc[i][2], acc[i][3]);
        if constexpr (OP == OP_QKV) {
            float bv = bias[m];
            r.x += bv; r.y += bv; r.z += bv; r.w += bv;
            size_t off = bz * STR_CN + (size_t)(m & 255) * NN + nbase;
            if (m < 256) {
                r.x *= 0.0625f; r.y *= 0.0625f; r.z *= 0.0625f; r.w *= 0.0625f;
                *reinterpret_cast<float4*>(&g_q[off]) = r;
            } else if (m < 512) {
                *reinterpret_cast<float4*>(&g_k[off]) = r;
            } else {
                *reinterpret_cast<float4*>(&g_v[off]) = r;
            }
        } else if constexpr (OP == OP_S) {
            *reinterpret_cast<float4*>(&g_S[bz * STR_NN + (size_t)m * NN + nbase]) = r;
        } else if constexpr (OP == OP_AV) {
            *reinterpret_cast<float4*>(&g_o[bz * STR_CN + (size_t)m * NN + nbase]) = r;
        } else {
            float bv = bias[m];
            size_t off = bz * STR_CN + (size_t)m * NN + nbase;
            float4 xr = *reinterpret_cast<const float4*>(&resid[off]);
            r.x += bv + xr.x; r.y += bv + xr.y; r.z += bv + xr.z; r.w += bv + xr.w;
            *reinterpret_cast<float4*>(&extOut[off]) = r;
        }
    }
}

// ===========================================================================
// Softmax (round-1 proven), in place on g_S
// ===========================================================================
__global__ void __launch_bounds__(256) softmax_kernel() {
    size_t row = blockIdx.x;
    float* p = g_S + row * NN;
    int tid = threadIdx.x;
    int lane = tid & 31, wid = tid >> 5;
    __shared__ float red[8];
    __shared__ float sh_bcast;

    float4 v[4];
    float mx = -INFINITY;
    #pragma unroll
    for (int i = 0; i < 4; i++) {
        v[i] = reinterpret_cast<float4*>(p)[tid + i * 256];
        mx = fmaxf(mx, fmaxf(fmaxf(v[i].x, v[i].y), fmaxf(v[i].z, v[i].w)));
    }
    #pragma unroll
    for (int o = 16; o; o >>= 1) mx = fmaxf(mx, __shfl_xor_sync(0xffffffffu, mx, o));
    if (lane == 0) red[wid] = mx;
    __syncthreads();
    if (tid == 0) {
        float m = red[0];
        #pragma unroll
        for (int i = 1; i < 8; i++) m = fmaxf(m, red[i]);
        sh_bcast = m;
    }
    __syncthreads();
    mx = sh_bcast;
    __syncthreads();

    float sum = 0.f;
    #pragma unroll
    for (int i = 0; i < 4; i++) {
        v[i].x = __expf(v[i].x - mx); v[i].y = __expf(v[i].y - mx);
        v[i].z = __expf(v[i].z - mx); v[i].w = __expf(v[i].w - mx);
        sum += v[i].x + v[i].y + v[i].z + v[i].w;
    }
    #pragma unroll
    for (int o = 16; o; o >>= 1) sum += __shfl_xor_sync(0xffffffffu, sum, o);
    if (lane == 0) red[wid] = sum;
    __syncthreads();
    if (tid == 0) {
        float s = 0.f;
        #pragma unroll
        for (int i = 0; i < 8; i++) s += red[i];
        sh_bcast = 1.0f / s;
    }
    __syncthreads();
    float inv = sh_bcast;

    #pragma unroll
    for (int i = 0; i < 4; i++) {
        v[i].x *= inv; v[i].y *= inv; v[i].z *= inv; v[i].w *= inv;
        reinterpret_cast<float4*>(p)[tid + i * 256] = v[i];
    }
}

// ===========================================================================
extern "C" void kernel_launch(void* const* d_in, const int* in_sizes, int n_in,
                              void* d_out, int out_size) {
    const float* x      = (const float*)d_in[0];
    const float* norm_w = (const float*)d_in[1];
    const float* norm_b = (const float*)d_in[2];
    const float* qkv_w  = (const float*)d_in[3];
    const float* qkv_b  = (const float*)d_in[4];
    const float* proj_w = (const float*)d_in[5];
    const float* proj_b = (const float*)d_in[6];
    float* out = (float*)d_out;

    // 1. GroupNorm -> g_xn
    gn_kernel<<<NB * NGRP, 256>>>(x, norm_w, norm_b);

    // 2. QKV GEMM (f32x2) -> g_q (scaled), g_k, g_v
    gemm2_kernel<OP_QKV><<<dim3(NN / 64, 768 / 128, NB), 256>>>(qkv_w, qkv_b, nullptr, nullptr);

    // 3. S = Q^T K (f32x2)
    gemm2_kernel<OP_S><<<dim3(NN / 64, NN / 128, NB), 256>>>(nullptr, nullptr, nullptr, nullptr);

    // 4. softmax (fp32, proven)
    softmax_kernel<<<NB * NN, 256>>>();

    // 5. O = V P^T (f32x2)
    gemm2_kernel<OP_AV><<<dim3(NN / 64, NC / 128, NB), 256>>>(nullptr, nullptr, nullptr, nullptr);

    // 6. proj + bias + residual (f32x2)
    gemm2_kernel<OP_PROJ><<<dim3(NN / 64, NC / 128, NB), 256>>>(proj_w, proj_b, x, out);
}